// round 12
// baseline (speedup 1.0000x reference)
#include <cuda_runtime.h>
#include <cuda_fp16.h>
#include <cstdint>

#define OHW      16384          // input plane (128*128)
#define NQ       65536          // output plane (256*256)
#define NPLANES  1024           // B*C
#define NTAPS    262144         // OHW * K * P
#define ROW      8              // padded slots per output pixel
#define G        3              // planes per CTA in gather kernel
#define MAIN_THREADS 1024
#define MAIN_CTAS    ((NPLANES + G - 1) / G)   // 342
#define SMEM_BYTES   (OHW * 8)                 // 128 KB: uint2 per input pixel
#define NITER        (NQ / MAIN_THREADS)       // 64

// Inverted-map scratch (device globals: allocation-free)
// entry: [31:16] w as fp16 bits, [15:14] k, [13:0] s   (0 == padding: w=0,s=0)
__device__ unsigned g_tab[NQ * ROW];   // 2 MB, zero-padded
__device__ int      g_cnt[NQ];
__device__ int      g_spill_n;
__device__ int4     g_spill[NTAPS];    // {q, s|k<<14, w_fp32_bits, 0}

__global__ void k_zero()
{
    int i = blockIdx.x * blockDim.x + threadIdx.x;
    int stride = gridDim.x * blockDim.x;
    uint4* t4 = reinterpret_cast<uint4*>(g_tab);
    const int NT4 = NQ * ROW / 4;                 // 131072
    for (int j = i; j < NT4; j += stride) t4[j] = make_uint4(0u, 0u, 0u, 0u);
    int4* c4 = reinterpret_cast<int4*>(g_cnt);
    for (int j = i; j < NQ / 4; j += stride) c4[j] = make_int4(0, 0, 0, 0);
    if (i == 0) g_spill_n = 0;
}

__global__ void k_build(const int* __restrict__ smap, const float* __restrict__ wts)
{
    int i = blockIdx.x * blockDim.x + threadIdx.x;
    if (i >= NTAPS) return;
    int q = smap[i];
    unsigned s = (unsigned)(i >> 4);              // tap layout: (s, k, p)
    unsigned k = (unsigned)((i >> 2) & 3);
    unsigned sk = s | (k << 14);
    float w = wts[i];
    int r = atomicAdd(&g_cnt[q], 1);
    if (r < ROW) {
        unsigned hw = (unsigned)__half_as_ushort(__float2half_rn(w));
        g_tab[q * ROW + r] = (hw << 16) | sk;
    } else {
        int j = atomicAdd(&g_spill_n, 1);
        g_spill[j] = make_int4(q, (int)sk, __float_as_int(w), 0);
    }
}

__global__ void __launch_bounds__(MAIN_THREADS)
k_main(const float* __restrict__ x, const int* __restrict__ mask, float* __restrict__ out)
{
    // One uint2 record per input pixel s:
    //   .x = x0_fp16 | x1_fp16<<16
    //   .y = x2_fp16 | (m0 | m1<<2 | m2<<4) << 16    (each m is 2 bits)
    extern __shared__ uint2 smv[];
    int tid = threadIdx.x;
    int p0 = blockIdx.x * G;
    int gmax = NPLANES - p0; if (gmax > G) gmax = G;

    {
        const float* xp0 = x    + (size_t)p0 * OHW;
        const int*   mp0 = mask + (size_t)p0 * OHW;
        for (int s = tid; s < OHW; s += MAIN_THREADS) {
            float xv0 = __ldg(xp0 + s);
            unsigned mm0 = (unsigned)__ldg(mp0 + s) & 3u;
            // Absent planes: x=0 so any phantom match contributes w*0 = 0.
            float xv1 = 0.f, xv2 = 0.f;
            unsigned mm1 = 0u, mm2 = 0u;
            if (gmax > 1) { xv1 = __ldg(xp0 + OHW + s);     mm1 = (unsigned)__ldg(mp0 + OHW + s) & 3u; }
            if (gmax > 2) { xv2 = __ldg(xp0 + 2 * OHW + s); mm2 = (unsigned)__ldg(mp0 + 2 * OHW + s) & 3u; }
            unsigned h0 = (unsigned)__half_as_ushort(__float2half_rn(xv0));
            unsigned h1 = (unsigned)__half_as_ushort(__float2half_rn(xv1));
            unsigned h2 = (unsigned)__half_as_ushort(__float2half_rn(xv2));
            unsigned mb = mm0 | (mm1 << 2) | (mm2 << 4);
            smv[s] = make_uint2(h0 | (h1 << 16), h2 | (mb << 16));
        }
    }
    __syncthreads();

    float* o0 = out + (size_t)p0 * NQ;
    float* o1 = o0 + NQ;
    float* o2 = o1 + NQ;

    const uint4* tab4 = reinterpret_cast<const uint4*>(g_tab);

    int q = tid;
    uint4 rlo = __ldg(tab4 + 2 * q);
    uint4 rhi = __ldg(tab4 + 2 * q + 1);

    #pragma unroll 1
    for (int i = 0; i < NITER; i++) {
        uint4 nlo, nhi;
        int qn = q + MAIN_THREADS;
        if (i < NITER - 1) {                      // uniform branch; prefetch next rows
            nlo = __ldg(tab4 + 2 * qn);
            nhi = __ldg(tab4 + 2 * qn + 1);
        }

        unsigned e[8] = { rlo.x, rlo.y, rlo.z, rlo.w, rhi.x, rhi.y, rhi.z, rhi.w };
        float a0 = 0.f, a1 = 0.f, a2 = 0.f;
        #pragma unroll
        for (int r = 0; r < ROW; r++) {
            unsigned ee = e[r];
            unsigned s_ = ee & 0x3FFFu;
            unsigned k_ = (ee >> 14) & 3u;
            float w = __half2float(__ushort_as_half((unsigned short)(ee >> 16)));
            uint2 v = smv[s_];                    // one LDS.64: 3 planes + masks
            unsigned mb = v.y >> 16;
            float2 x01 = __half22float2(*reinterpret_cast<const __half2*>(&v.x));
            float  x2  = __half2float(__ushort_as_half((unsigned short)(v.y & 0xFFFFu)));
            a0 += ((mb        & 3u) == k_) ? w * x01.x : 0.f;
            a1 += (((mb >> 2) & 3u) == k_) ? w * x01.y : 0.f;
            a2 += (((mb >> 4) & 3u) == k_) ? w * x2    : 0.f;
        }
        o0[q] = a0;
        if (gmax > 1) o1[q] = a1;
        if (gmax > 2) o2[q] = a2;

        rlo = nlo; rhi = nhi; q = qn;
    }

    // Spill pass: rare overflow entries, planes already in SMEM.
    // NOTE: atomics MUST be gmax-guarded (tail CTA has <G planes).
    __syncthreads();                              // order plain stores before atomics
    int n = g_spill_n;
    for (int j = tid; j < n; j += MAIN_THREADS) {
        int4 e = g_spill[j];
        unsigned sk = (unsigned)e.y;
        unsigned s_ = sk & 0x3FFFu;
        unsigned k_ = (sk >> 14) & 3u;
        float w = __int_as_float(e.z);
        uint2 v = smv[s_];
        unsigned mb = v.y >> 16;
        float2 x01 = __half22float2(*reinterpret_cast<const __half2*>(&v.x));
        float  x2  = __half2float(__ushort_as_half((unsigned short)(v.y & 0xFFFFu)));
        if ((mb & 3u) == k_)                          atomicAdd(o0 + e.x, w * x01.x);
        if (gmax > 1 && ((mb >> 2) & 3u) == k_)       atomicAdd(o1 + e.x, w * x01.y);
        if (gmax > 2 && ((mb >> 4) & 3u) == k_)       atomicAdd(o2 + e.x, w * x2);
    }
}

extern "C" void kernel_launch(void* const* d_in, const int* in_sizes, int n_in,
                              void* d_out, int out_size)
{
    const float* x    = (const float*)d_in[0];
    const int*   mask = (const int*)d_in[1];
    const int*   smap = (const int*)d_in[2];
    const float* wts  = (const float*)d_in[3];
    float* out = (float*)d_out;

    cudaFuncSetAttribute(k_main, cudaFuncAttributeMaxDynamicSharedMemorySize, SMEM_BYTES);

    k_zero<<<256, 256>>>();
    k_build<<<NTAPS / 256, 256>>>(smap, wts);
    k_main<<<MAIN_CTAS, MAIN_THREADS, SMEM_BYTES>>>(x, mask, out);
}

// round 13
// speedup vs baseline: 1.4429x; 1.4429x over previous
#include <cuda_runtime.h>
#include <cuda_fp16.h>
#include <cstdint>

#define OHW      16384          // input plane (128*128)
#define NQ       65536          // output plane (256*256)
#define NPLANES  1024           // B*C
#define NTAPS    262144         // OHW * K * P
#define ROW      8              // padded slots per output pixel
#define G        3              // planes per CTA group
#define NGROUPS  ((NPLANES + G - 1) / G)       // 342
#define QSPLIT   2
#define MAIN_THREADS 1024
#define MAIN_CTAS    (NGROUPS * QSPLIT)        // 684
#define SMEM_BYTES   (OHW * 8)                 // 128 KB: uint2 per input pixel
#define NITER        (NQ / QSPLIT / MAIN_THREADS)   // 32

// Inverted-map scratch (device globals: allocation-free)
// entry: [31:16] w as fp16 bits, [15:14] k, [13:0] s   (0 == padding: w=0,s=0)
__device__ unsigned g_tab[NQ * ROW];   // 2 MB, zero-padded
__device__ int      g_cnt[NQ];
__device__ int      g_spill_n;
__device__ int4     g_spill[NTAPS];    // {q, s|k<<14, w_fp32_bits, 0}

__global__ void k_zero()
{
    int i = blockIdx.x * blockDim.x + threadIdx.x;
    int stride = gridDim.x * blockDim.x;
    uint4* t4 = reinterpret_cast<uint4*>(g_tab);
    const int NT4 = NQ * ROW / 4;                 // 131072
    for (int j = i; j < NT4; j += stride) t4[j] = make_uint4(0u, 0u, 0u, 0u);
    int4* c4 = reinterpret_cast<int4*>(g_cnt);
    for (int j = i; j < NQ / 4; j += stride) c4[j] = make_int4(0, 0, 0, 0);
    if (i == 0) g_spill_n = 0;
}

__global__ void k_build(const int* __restrict__ smap, const float* __restrict__ wts)
{
    int i = blockIdx.x * blockDim.x + threadIdx.x;
    if (i >= NTAPS) return;
    int q = smap[i];
    unsigned s = (unsigned)(i >> 4);              // tap layout: (s, k, p)
    unsigned k = (unsigned)((i >> 2) & 3);
    unsigned sk = s | (k << 14);
    float w = wts[i];
    int r = atomicAdd(&g_cnt[q], 1);
    if (r < ROW) {
        unsigned hw = (unsigned)__half_as_ushort(__float2half_rn(w));
        g_tab[q * ROW + r] = (hw << 16) | sk;
    } else {
        int j = atomicAdd(&g_spill_n, 1);
        g_spill[j] = make_int4(q, (int)sk, __float_as_int(w), 0);
    }
}

// Predicated FFMA: @p acc += w*x  (forces @P FFMA, no FSEL/branch)
#define PFMA(acc, cond0, w_, x_)                                          \
    asm("{\n\t.reg .pred p;\n\tsetp.eq.u32 p, %1, 0;\n\t"                 \
        "@p fma.rn.f32 %0, %2, %3, %0;\n\t}"                              \
        : "+f"(acc) : "r"(cond0), "f"(w_), "f"(x_))

__global__ void __launch_bounds__(MAIN_THREADS)
k_main(const float* __restrict__ x, const int* __restrict__ mask, float* __restrict__ out)
{
    // One uint2 record per input pixel s:
    //   .x = x0_fp16 | x1_fp16<<16
    //   .y = x2_fp16 | (m0 | m1<<2 | m2<<4) << 16    (each m is 2 bits)
    extern __shared__ uint2 smv[];
    int tid  = threadIdx.x;
    int grp  = blockIdx.x >> 1;
    int half = blockIdx.x & 1;
    int p0 = grp * G;
    int gmax = NPLANES - p0; if (gmax > G) gmax = G;

    {
        const float* xp0 = x    + (size_t)p0 * OHW;
        const int*   mp0 = mask + (size_t)p0 * OHW;
        for (int s = tid; s < OHW; s += MAIN_THREADS) {
            float xv0 = __ldg(xp0 + s);
            unsigned mm0 = (unsigned)__ldg(mp0 + s) & 3u;
            // Absent planes: x=0 so any phantom match contributes w*0 = 0.
            float xv1 = 0.f, xv2 = 0.f;
            unsigned mm1 = 0u, mm2 = 0u;
            if (gmax > 1) { xv1 = __ldg(xp0 + OHW + s);     mm1 = (unsigned)__ldg(mp0 + OHW + s) & 3u; }
            if (gmax > 2) { xv2 = __ldg(xp0 + 2 * OHW + s); mm2 = (unsigned)__ldg(mp0 + 2 * OHW + s) & 3u; }
            unsigned h0 = (unsigned)__half_as_ushort(__float2half_rn(xv0));
            unsigned h1 = (unsigned)__half_as_ushort(__float2half_rn(xv1));
            unsigned h2 = (unsigned)__half_as_ushort(__float2half_rn(xv2));
            unsigned mb = mm0 | (mm1 << 2) | (mm2 << 4);
            smv[s] = make_uint2(h0 | (h1 << 16), h2 | (mb << 16));
        }
    }
    __syncthreads();

    float* o0 = out + (size_t)p0 * NQ;
    float* o1 = o0 + NQ;
    float* o2 = o1 + NQ;

    const uint4* tab4 = reinterpret_cast<const uint4*>(g_tab);

    int q = tid + half * (NQ / QSPLIT);
    uint4 rlo = __ldg(tab4 + 2 * q);
    uint4 rhi = __ldg(tab4 + 2 * q + 1);

    #pragma unroll 1
    for (int i = 0; i < NITER; i++) {
        uint4 nlo, nhi;
        int qn = q + MAIN_THREADS;
        if (i < NITER - 1) {                      // uniform branch; prefetch next rows
            nlo = __ldg(tab4 + 2 * qn);
            nhi = __ldg(tab4 + 2 * qn + 1);
        }

        unsigned e[8] = { rlo.x, rlo.y, rlo.z, rlo.w, rhi.x, rhi.y, rhi.z, rhi.w };
        float a0 = 0.f, a1 = 0.f, a2 = 0.f;
        #pragma unroll
        for (int r = 0; r < ROW; r++) {
            unsigned ee = e[r];
            unsigned s_ = ee & 0x3FFFu;
            uint2 v = smv[s_];                    // one LDS.64: 3 planes + masks
            unsigned kk3 = ((ee >> 14) & 3u) * 21u;  // k replicated into 3 2-bit fields
            unsigned d = (v.y >> 16) ^ kk3;          // 2-bit field g == 0 iff m_g == k
            float w = __half2float(__ushort_as_half((unsigned short)(ee >> 16)));
            float2 x01 = __half22float2(*reinterpret_cast<const __half2*>(&v.x));
            float  x2  = __half2float(__ushort_as_half((unsigned short)(v.y & 0xFFFFu)));
            PFMA(a0, d & 3u,         w, x01.x);
            PFMA(a1, d & 12u,        w, x01.y);
            PFMA(a2, d & 48u,        w, x2);
        }
        o0[q] = a0;
        if (gmax > 1) o1[q] = a1;
        if (gmax > 2) o2[q] = a2;

        rlo = nlo; rhi = nhi; q = qn;
    }

    // Spill pass: rare overflow entries; only the half==0 CTA of each group
    // applies them (planes are in SMEM; avoids double-adds across the q-split).
    __syncthreads();                              // order plain stores before atomics
    if (half == 0) {
        int n = g_spill_n;
        for (int j = tid; j < n; j += MAIN_THREADS) {
            int4 e = g_spill[j];
            unsigned sk = (unsigned)e.y;
            unsigned s_ = sk & 0x3FFFu;
            unsigned k_ = (sk >> 14) & 3u;
            float w = __int_as_float(e.z);
            uint2 v = smv[s_];
            unsigned mb = v.y >> 16;
            float2 x01 = __half22float2(*reinterpret_cast<const __half2*>(&v.x));
            float  x2  = __half2float(__ushort_as_half((unsigned short)(v.y & 0xFFFFu)));
            if ((mb & 3u) == k_)                     atomicAdd(o0 + e.x, w * x01.x);
            if (gmax > 1 && ((mb >> 2) & 3u) == k_)  atomicAdd(o1 + e.x, w * x01.y);
            if (gmax > 2 && ((mb >> 4) & 3u) == k_)  atomicAdd(o2 + e.x, w * x2);
        }
    }
}

extern "C" void kernel_launch(void* const* d_in, const int* in_sizes, int n_in,
                              void* d_out, int out_size)
{
    const float* x    = (const float*)d_in[0];
    const int*   mask = (const int*)d_in[1];
    const int*   smap = (const int*)d_in[2];
    const float* wts  = (const float*)d_in[3];
    float* out = (float*)d_out;

    cudaFuncSetAttribute(k_main, cudaFuncAttributeMaxDynamicSharedMemorySize, SMEM_BYTES);

    k_zero<<<256, 256>>>();
    k_build<<<NTAPS / 256, 256>>>(smap, wts);
    k_main<<<MAIN_CTAS, MAIN_THREADS, SMEM_BYTES>>>(x, mask, out);
}